// round 6
// baseline (speedup 1.0000x reference)
#include <cuda_runtime.h>
#include <stdint.h>

typedef unsigned long long ull;

// ---------- f32x2 packed-fp32 helpers ----------
__device__ __forceinline__ ull pk2(float lo, float hi) {
    ull r; asm("mov.b64 %0,{%1,%2};" : "=l"(r) : "f"(lo), "f"(hi)); return r;
}
__device__ __forceinline__ void upk2(ull v, float& lo, float& hi) {
    asm("mov.b64 {%0,%1},%2;" : "=f"(lo), "=f"(hi) : "l"(v));
}
__device__ __forceinline__ ull ffma2(ull a, ull b, ull c) {
    ull d; asm("fma.rn.f32x2 %0,%1,%2,%3;" : "=l"(d) : "l"(a), "l"(b), "l"(c)); return d;
}

// ---------- L2 sync primitives ----------
__device__ __forceinline__ unsigned ld_acq_u32(const unsigned* p) {
    unsigned v;
    asm volatile("ld.acquire.gpu.global.u32 %0, [%1];" : "=r"(v) : "l"(p) : "memory");
    return v;
}
__device__ __forceinline__ void st_rel_u32(unsigned* p, unsigned v) {
    asm volatile("st.release.gpu.global.u32 [%0], %1;" :: "l"(p), "r"(v) : "memory");
}
__device__ __forceinline__ float ld_rlx_f32(const float* p) {
    float v;
    asm volatile("ld.relaxed.gpu.global.f32 %0, [%1];" : "=f"(v) : "l"(p) : "memory");
    return v;
}
__device__ __forceinline__ void st_rlx_f32(float* p, float v) {
    asm volatile("st.relaxed.gpu.global.f32 [%0], %1;" :: "l"(p), "f"(v) : "memory");
}

// ---------- problem constants ----------
#define BATCH   64
#define SEQ     2048
#define FEAT    256
#define HID     256
#define G4      1024           // 4*HID
#define BG      4              // batches per group
#define NCTA_PG 8              // CTAs per group
#define NGROUP  16

// ---------- scratch ----------
__device__ float    h_gbuf[NGROUP][2][BG][HID];     // plain h, [grp][parity][b][k]
__device__ unsigned sent_buf[NGROUP][NCTA_PG][32];  // sentinels, 128B stride

// ============================================================
// init: zero parity-0 h (t=0 reads zeros) + all sentinels.
// parity-1 reads are gated by fresh sentinels each run.
// ============================================================
__global__ void init_kernel() {
    int t = blockIdx.x * blockDim.x + threadIdx.x;
    if (t < NGROUP * BG * HID) {
        int g = t / (BG * HID);
        int rem = t % (BG * HID);
        h_gbuf[g][0][rem / HID][rem % HID] = 0.0f;
    }
    if (t < NGROUP * NCTA_PG) {
        sent_buf[t >> 3][t & 7][0] = 0u;
    }
}

// ============================================================
// Fused LSTM: 16 groups x 8 CTAs. gates(t) = [x(t),h(t)] @ [WX;WH].
// WH slice in 128 REGISTERS/thread; WX slice pre-packed in SMEM.
// Sync: one release-sentinel per CTA per step (8 words/group),
// polled by ONE warp with acquire loads; h data travels as plain
// coalesced fp32 through L2. xp-GEMM(t+1) fills the publish window.
// ============================================================
__device__ __forceinline__ float fsig(float x) {
    return __fdividef(1.0f, 1.0f + __expf(-x));
}
__device__ __forceinline__ float ftanh(float x) { return 2.0f * fsig(2.0f * x) - 1.0f; }

__global__ __launch_bounds__(256, 1)
void lstm_kernel(float* __restrict__ out,
                 const float* __restrict__ x,
                 const float* __restrict__ WX,
                 const float* __restrict__ WH,
                 const float* __restrict__ BX,
                 const float* __restrict__ BH,
                 long long out_size)
{
    extern __shared__ char smem[];
    ulonglong2* wx_s    = (ulonglong2*)smem;                    // [256][32] (wA,wB)  128 KB
    ull*        hd      = (ull*)(smem + 131072);                // [256][4] (h,h)      8 KB
    ull*        xd      = (ull*)(smem + 131072 + 8192);         // [2][256][4] (x,x)  16 KB
    float4*     red_s   = (float4*)(smem + 131072 + 8192 + 16384);  // [4][256]       16 KB
    float*      gates_s = (float*)(smem + 131072 + 8192 + 16384 + 16384); // [4][128]  2 KB

    const int tid = threadIdx.x;
    const int grp = blockIdx.x >> 3;
    const int r   = blockIdx.x & 7;
    const int batch0 = grp * BG;

    const int ks = tid >> 5;            // K-split warp 0..7
    const int cq = tid & 31;            // col-quad (local cols 4cq..4cq+3)
    const int rb = tid >> 5;            // act batch (tid<128)
    const int rc = tid & 31;            // act hidden unit / reducer col-quad

    // ---- load WX slice into SMEM, pre-packed (wA,wB) ----
    for (int idx = tid; idx < 256 * 32; idx += 256) {
        int f = idx >> 5, ci = idx & 31;
        int gc = (ci >> 3) * HID + 32 * r + ((4 * ci) & 31);
        float4 w4 = *(const float4*)&WX[(size_t)f * G4 + gc];
        wx_s[idx] = make_ulonglong2(pk2(w4.x, w4.y), pk2(w4.z, w4.w));
    }

    // ---- load WH slice into registers (f32x2-packed col pairs) ----
    ull wA[32], wB[32];
    {
        const int gc = (cq >> 3) * HID + 32 * r + ((4 * cq) & 31);
        const float* wp = WH + (size_t)(32 * ks) * G4 + gc;
#pragma unroll
        for (int kk = 0; kk < 32; kk++) {
            float4 w4 = *(const float4*)(wp + (size_t)kk * G4);
            wA[kk] = pk2(w4.x, w4.y);
            wB[kk] = pk2(w4.z, w4.w);
        }
    }

    // ---- bias (folded once): per (rb,rc) thread, 4 gate cols ----
    float4 bias4 = make_float4(0.f, 0.f, 0.f, 0.f);
    if (tid < 128) {
        int gc = (rc >> 3) * HID + 32 * r + ((4 * rc) & 31);
        float4 bx4 = *(const float4*)&BX[gc];
        float4 bh4 = *(const float4*)&BH[gc];
        bias4 = make_float4(bx4.x + bh4.x, bx4.y + bh4.y, bx4.z + bh4.z, bx4.w + bh4.w);
    }

    // ---- x prefetch: thread owns feat=tid, 4 batches ----
    const float* xp0 = x + (size_t)batch0 * SEQ * FEAT + tid;
    float xr0, xr1, xr2, xr3;
    {   // x(0) -> xd[0] directly
        float a0 = xp0[0 * (size_t)SEQ * FEAT];
        float a1 = xp0[1 * (size_t)SEQ * FEAT];
        float a2 = xp0[2 * (size_t)SEQ * FEAT];
        float a3 = xp0[3 * (size_t)SEQ * FEAT];
        ull* xw = xd + (size_t)tid * BG;                    // parity 0
        *(ulonglong2*)(xw + 0) = make_ulonglong2(pk2(a0, a0), pk2(a1, a1));
        *(ulonglong2*)(xw + 2) = make_ulonglong2(pk2(a2, a2), pk2(a3, a3));
    }
    // x(1) -> regs
    xr0 = xp0[(size_t)1 * FEAT + 0 * (size_t)SEQ * FEAT];
    xr1 = xp0[(size_t)1 * FEAT + 1 * (size_t)SEQ * FEAT];
    xr2 = xp0[(size_t)1 * FEAT + 2 * (size_t)SEQ * FEAT];
    xr3 = xp0[(size_t)1 * FEAT + 3 * (size_t)SEQ * FEAT];

    __syncthreads();   // wx_s + xd[0] visible

    // ---- accumulators: xp-partials(t) live here between iterations ----
    ull a00, a01, a10, a11, a20, a21, a30, a31;

    // ---- prologue: xp-GEMM(0) ----
    a00 = a01 = a10 = a11 = a20 = a21 = a30 = a31 = pk2(0.f, 0.f);
    {
        const ull* xp_ = xd + (size_t)(ks * 32) * BG;       // parity 0
        const ulonglong2* wp = wx_s + (size_t)(ks * 32) * 32 + cq;
#pragma unroll
        for (int kk = 0; kk < 32; kk++) {
            ulonglong2 d0 = *(const ulonglong2*)(xp_ + kk * 4);
            ulonglong2 d1 = *(const ulonglong2*)(xp_ + kk * 4 + 2);
            ulonglong2 w2 = wp[kk * 32];
            a00 = ffma2(d0.x, w2.x, a00); a01 = ffma2(d0.x, w2.y, a01);
            a10 = ffma2(d0.y, w2.x, a10); a11 = ffma2(d0.y, w2.y, a11);
            a20 = ffma2(d1.x, w2.x, a20); a21 = ffma2(d1.x, w2.y, a21);
            a30 = ffma2(d1.y, w2.x, a30); a31 = ffma2(d1.y, w2.y, a31);
        }
    }

    float cstate = 0.0f, hlast = 0.0f;

    for (int t = 0; t < SEQ; t++) {
        // ---- stage x(t+1) -> xd[(t+1)&1] ----
        {
            ull* xw = xd + ((size_t)((t + 1) & 1) * HID + tid) * BG;
            *(ulonglong2*)(xw + 0) = make_ulonglong2(pk2(xr0, xr0), pk2(xr1, xr1));
            *(ulonglong2*)(xw + 2) = make_ulonglong2(pk2(xr2, xr2), pk2(xr3, xr3));
        }

        // ---- poll 8 sentinels (warp 0 only, acquire) ----
        if (tid < 32) {
            const unsigned tg = (unsigned)t;
            bool ok;
            do {
                unsigned s = 0xFFFFFFFFu;
                if (tid < NCTA_PG) s = ld_acq_u32(&sent_buf[grp][tid][0]);
                ok = __all_sync(0xFFFFFFFFu, s >= tg);
            } while (!ok);
        }
        __syncthreads();   // chain acquire to whole CTA

        // ---- gather h(t) (plain fp32, coalesced) and dup-pack to SMEM ----
        {
            const float* hb = &h_gbuf[grp][t & 1][0][0];
            float h0 = ld_rlx_f32(hb + 0 * HID + tid);
            float h1 = ld_rlx_f32(hb + 1 * HID + tid);
            float h2 = ld_rlx_f32(hb + 2 * HID + tid);
            float h3 = ld_rlx_f32(hb + 3 * HID + tid);
            ull* hw = hd + (size_t)tid * BG;
            *(ulonglong2*)(hw + 0) = make_ulonglong2(pk2(h0, h0), pk2(h1, h1));
            *(ulonglong2*)(hw + 2) = make_ulonglong2(pk2(h2, h2), pk2(h3, h3));
        }
        __syncthreads();

        // ---- h-GEMM: accumulate onto xp-partials(t) already in acc ----
        {
            const ull* hp = hd + (size_t)(ks * 32) * BG;
#pragma unroll
            for (int kk = 0; kk < 32; kk++) {
                ulonglong2 d0 = *(const ulonglong2*)(hp + kk * 4);
                ulonglong2 d1 = *(const ulonglong2*)(hp + kk * 4 + 2);
                a00 = ffma2(d0.x, wA[kk], a00); a01 = ffma2(d0.x, wB[kk], a01);
                a10 = ffma2(d0.y, wA[kk], a10); a11 = ffma2(d0.y, wB[kk], a11);
                a20 = ffma2(d1.x, wA[kk], a20); a21 = ffma2(d1.x, wB[kk], a21);
                a30 = ffma2(d1.y, wA[kk], a30); a31 = ffma2(d1.y, wB[kk], a31);
            }
        }
        {   // stage partials
            float4 v;
            upk2(a00, v.x, v.y); upk2(a01, v.z, v.w); red_s[0 * 256 + tid] = v;
            upk2(a10, v.x, v.y); upk2(a11, v.z, v.w); red_s[1 * 256 + tid] = v;
            upk2(a20, v.x, v.y); upk2(a21, v.z, v.w); red_s[2 * 256 + tid] = v;
            upk2(a30, v.x, v.y); upk2(a31, v.z, v.w); red_s[3 * 256 + tid] = v;
        }
        __syncthreads();

        // ---- reduce(+bias) -> gates ----
        if (tid < 128) {
            float4 s = bias4;
#pragma unroll
            for (int j = 0; j < 8; j++) {
                float4 v = red_s[rb * 256 + j * 32 + rc];
                s.x += v.x; s.y += v.y; s.z += v.z; s.w += v.w;
            }
            *(float4*)&gates_s[rb * 128 + 4 * rc] = s;
        }
        __syncwarp();
        if (tid < 128) {
            float gi = gates_s[rb * 128 +       rc];
            float gf = gates_s[rb * 128 +  32 + rc];
            float gg = gates_s[rb * 128 +  64 + rc];
            float go = gates_s[rb * 128 +  96 + rc];
            float i_ = fsig(gi), f_ = fsig(gf), g_ = ftanh(gg), o_ = fsig(go);
            cstate = f_ * cstate + i_ * g_;
            float h_ = o_ * ftanh(cstate);
            hlast = h_;
            const int kidx = 32 * r + rc;
            st_rlx_f32(&h_gbuf[grp][(t + 1) & 1][rb][kidx], h_);   // coalesced per warp
            out[((size_t)(batch0 + rb) * SEQ + t) * HID + kidx] = h_;
        }
        __syncthreads();   // all h stores done before sentinel

        // ---- publish sentinel (release) ----
        if (tid == 0) st_rel_u32(&sent_buf[grp][r][0], (unsigned)(t + 1));

        // ---- prefetch x(t+2) ----
        {
            size_t tn = (size_t)((t + 2 < SEQ) ? (t + 2) : t) * FEAT;
            xr0 = xp0[tn + 0 * (size_t)SEQ * FEAT];
            xr1 = xp0[tn + 1 * (size_t)SEQ * FEAT];
            xr2 = xp0[tn + 2 * (size_t)SEQ * FEAT];
            xr3 = xp0[tn + 3 * (size_t)SEQ * FEAT];
        }

        // ---- xp-GEMM(t+1): fills the publish->poll latency window ----
        a00 = a01 = a10 = a11 = a20 = a21 = a30 = a31 = pk2(0.f, 0.f);
        {
            const ull* xp_ = xd + ((size_t)((t + 1) & 1) * HID + ks * 32) * BG;
            const ulonglong2* wp = wx_s + (size_t)(ks * 32) * 32 + cq;
#pragma unroll
            for (int kk = 0; kk < 32; kk++) {
                ulonglong2 d0 = *(const ulonglong2*)(xp_ + kk * 4);
                ulonglong2 d1 = *(const ulonglong2*)(xp_ + kk * 4 + 2);
                ulonglong2 w2 = wp[kk * 32];
                a00 = ffma2(d0.x, w2.x, a00); a01 = ffma2(d0.x, w2.y, a01);
                a10 = ffma2(d0.y, w2.x, a10); a11 = ffma2(d0.y, w2.y, a11);
                a20 = ffma2(d1.x, w2.x, a20); a21 = ffma2(d1.x, w2.y, a21);
                a30 = ffma2(d1.y, w2.x, a30); a31 = ffma2(d1.y, w2.y, a31);
            }
        }
    }

    // ---- h_n (second output region) ----
    if (tid < 128 && out_size >= (long long)BATCH * SEQ * HID + BATCH * HID) {
        out[(size_t)BATCH * SEQ * HID + (size_t)(batch0 + rb) * HID + 32 * r + rc] = hlast;
    }
}

// ============================================================
extern "C" void kernel_launch(void* const* d_in, const int* in_sizes, int n_in,
                              void* d_out, int out_size)
{
    const float* x  = (const float*)d_in[0];
    const float* WX = (const float*)d_in[1];
    const float* WH = (const float*)d_in[2];
    const float* BX = (const float*)d_in[3];
    const float* BH = (const float*)d_in[4];
    float* out = (float*)d_out;

    const size_t smem_bytes = 131072 + 8192 + 16384 + 16384 + 2048;  // 174080
    cudaFuncSetAttribute(lstm_kernel, cudaFuncAttributeMaxDynamicSharedMemorySize,
                         (int)smem_bytes);

    init_kernel<<<64, 256>>>();
    lstm_kernel<<<NGROUP * NCTA_PG, 256, smem_bytes>>>(
        out, x, WX, WH, BX, BH, (long long)out_size);
}

// round 7
// speedup vs baseline: 1.3241x; 1.3241x over previous
#include <cuda_runtime.h>
#include <stdint.h>

typedef unsigned long long ull;

// ---------- f32x2 packed-fp32 helpers ----------
__device__ __forceinline__ ull pk2(float lo, float hi) {
    ull r; asm("mov.b64 %0,{%1,%2};" : "=l"(r) : "f"(lo), "f"(hi)); return r;
}
__device__ __forceinline__ void upk2(ull v, float& lo, float& hi) {
    asm("mov.b64 {%0,%1},%2;" : "=f"(lo), "=f"(hi) : "l"(v));
}
__device__ __forceinline__ ull ffma2(ull a, ull b, ull c) {
    ull d; asm("fma.rn.f32x2 %0,%1,%2,%3;" : "=l"(d) : "l"(a), "l"(b), "l"(c)); return d;
}
__device__ __forceinline__ ull fadd2(ull a, ull b) {
    ull d; asm("add.rn.f32x2 %0,%1,%2;" : "=l"(d) : "l"(a), "l"(b)); return d;
}

// ---------- relaxed 64-bit L2 atoms (tag+data fused in one word) ----------
__device__ __forceinline__ ull ld_rlx(const ull* p) {
    ull v;
    asm volatile("ld.relaxed.gpu.global.u64 %0, [%1];" : "=l"(v) : "l"(p) : "memory");
    return v;
}
__device__ __forceinline__ void st_rlx(ull* p, ull v) {
    asm volatile("st.relaxed.gpu.global.u64 [%0], %1;" :: "l"(p), "l"(v) : "memory");
}

// ---------- problem constants ----------
#define BATCH   64
#define SEQ     2048
#define FEAT    256
#define HID     256
#define G4      1024           // 4*HID
#define BG      4              // batches per group
#define NCTA_PG 8              // CTAs per group
#define NGROUP  16

// ---------- scratch ----------
__device__ ull ht_buf[NGROUP * 2 * HID * BG];   // tagged h: lo=h bits, hi=step tag

// ============================================================
__global__ void init_kernel() {
    int t = blockIdx.x * blockDim.x + threadIdx.x;
    if (t < NGROUP * HID * BG) {
        int grp = t / (HID * BG);
        int rem = t % (HID * BG);
        ht_buf[(size_t)grp * 2 * HID * BG + rem] = 0ull;   // parity-0: tag 0, h=0
    }
}

// ============================================================
// Fused LSTM: 16 groups x 8 CTAs. gates(t)=[x(t),h(t)]@[WX;WH].
// WH slice in 128 regs/thread; WX pre-packed in SMEM.
// KEY: warp w's K-split == producer CTA w. Each warp polls ONLY
// its producer's tagged words (fused tag+data), packs its own hd
// region, __syncwarp, and starts its GEMM chunk — no CTA-wide
// poll barrier. red_s parity double-buffered to licence this.
// ============================================================
__device__ __forceinline__ float fsig(float x) {
    return __fdividef(1.0f, 1.0f + __expf(-x));
}
__device__ __forceinline__ float ftanh(float x) { return 2.0f * fsig(2.0f * x) - 1.0f; }

__global__ __launch_bounds__(256, 1)
void lstm_kernel(float* __restrict__ out,
                 const float* __restrict__ x,
                 const float* __restrict__ WX,
                 const float* __restrict__ WH,
                 const float* __restrict__ BX,
                 const float* __restrict__ BH,
                 long long out_size)
{
    extern __shared__ char smem[];
    ulonglong2* wx_s    = (ulonglong2*)smem;                         // [256][32]      128 KB
    ull*        hd      = (ull*)(smem + 131072);                     // [256][4]         8 KB
    ull*        xd      = (ull*)(smem + 131072 + 8192);              // [2][256][4]     16 KB
    ulonglong2* red_u   = (ulonglong2*)(smem + 131072 + 8192 + 16384);  // [2][4][256]  32 KB
    float*      gates_s = (float*)(smem + 131072 + 8192 + 16384 + 32768); // [4][128]    2 KB

    const int tid = threadIdx.x;
    const int grp = blockIdx.x >> 3;
    const int r   = blockIdx.x & 7;
    const int batch0 = grp * BG;

    const int ks   = tid >> 5;           // K-split warp id == producer CTA id
    const int lane = tid & 31;
    const int cq   = lane;               // col-quad (local cols 4cq..4cq+3)
    const int rb   = tid >> 5;           // act/reduce batch (tid<128)
    const int rc   = lane;               // act hidden unit / reducer col-quad
    const int kown = 32 * ks + lane;     // the k-slot this thread polls/packs

    // ---- load WX slice into SMEM, pre-packed (wA,wB) ----
    for (int idx = tid; idx < 256 * 32; idx += 256) {
        int f = idx >> 5, ci = idx & 31;
        int gc = (ci >> 3) * HID + 32 * r + ((4 * ci) & 31);
        float4 w4 = *(const float4*)&WX[(size_t)f * G4 + gc];
        wx_s[idx] = make_ulonglong2(pk2(w4.x, w4.y), pk2(w4.z, w4.w));
    }

    // ---- load WH slice into registers ----
    ull wA[32], wB[32];
    {
        const int gc = (cq >> 3) * HID + 32 * r + ((4 * cq) & 31);
        const float* wp = WH + (size_t)(32 * ks) * G4 + gc;
#pragma unroll
        for (int kk = 0; kk < 32; kk++) {
            float4 w4 = *(const float4*)(wp + (size_t)kk * G4);
            wA[kk] = pk2(w4.x, w4.y);
            wB[kk] = pk2(w4.z, w4.w);
        }
    }

    // ---- bias, packed f32x2 (folded once) ----
    ull biasA = pk2(0.f, 0.f), biasB = biasA;
    if (tid < 128) {
        int gc = (rc >> 3) * HID + 32 * r + ((4 * rc) & 31);
        float4 bx4 = *(const float4*)&BX[gc];
        float4 bh4 = *(const float4*)&BH[gc];
        biasA = pk2(bx4.x + bh4.x, bx4.y + bh4.y);
        biasB = pk2(bx4.z + bh4.z, bx4.w + bh4.w);
    }

    // ---- x prefetch: thread owns feat=tid, 4 batches ----
    const float* xp0 = x + (size_t)batch0 * SEQ * FEAT + tid;
    float xr0, xr1, xr2, xr3;
    {   // x(0) -> xd[0]
        float a0 = xp0[0 * (size_t)SEQ * FEAT];
        float a1 = xp0[1 * (size_t)SEQ * FEAT];
        float a2 = xp0[2 * (size_t)SEQ * FEAT];
        float a3 = xp0[3 * (size_t)SEQ * FEAT];
        ull* xw = xd + (size_t)tid * BG;
        *(ulonglong2*)(xw + 0) = make_ulonglong2(pk2(a0, a0), pk2(a1, a1));
        *(ulonglong2*)(xw + 2) = make_ulonglong2(pk2(a2, a2), pk2(a3, a3));
    }
    xr0 = xp0[(size_t)1 * FEAT + 0 * (size_t)SEQ * FEAT];
    xr1 = xp0[(size_t)1 * FEAT + 1 * (size_t)SEQ * FEAT];
    xr2 = xp0[(size_t)1 * FEAT + 2 * (size_t)SEQ * FEAT];
    xr3 = xp0[(size_t)1 * FEAT + 3 * (size_t)SEQ * FEAT];

    __syncthreads();   // wx_s + xd[0] visible

    ull* ht = &ht_buf[(size_t)grp * 2 * HID * BG];   // [parity][k][b]

    ull a00, a01, a10, a11, a20, a21, a30, a31;

    // ---- prologue: xp-GEMM(0) ----
    a00 = a01 = a10 = a11 = a20 = a21 = a30 = a31 = pk2(0.f, 0.f);
    {
        const ull* xp_ = xd + (size_t)(ks * 32) * BG;
        const ulonglong2* wp = wx_s + (size_t)(ks * 32) * 32 + cq;
#pragma unroll
        for (int kk = 0; kk < 32; kk++) {
            ulonglong2 d0 = *(const ulonglong2*)(xp_ + kk * 4);
            ulonglong2 d1 = *(const ulonglong2*)(xp_ + kk * 4 + 2);
            ulonglong2 w2 = wp[kk * 32];
            a00 = ffma2(d0.x, w2.x, a00); a01 = ffma2(d0.x, w2.y, a01);
            a10 = ffma2(d0.y, w2.x, a10); a11 = ffma2(d0.y, w2.y, a11);
            a20 = ffma2(d1.x, w2.x, a20); a21 = ffma2(d1.x, w2.y, a21);
            a30 = ffma2(d1.y, w2.x, a30); a31 = ffma2(d1.y, w2.y, a31);
        }
    }

    float cstate = 0.0f, hlast = 0.0f;

    for (int t = 0; t < SEQ; t++) {
        const int par = t & 1;

        // ---- stage x(t+1) -> xd[par^1] (own slot; read later by own warp) ----
        {
            ull* xw = xd + ((size_t)(par ^ 1) * HID + tid) * BG;
            *(ulonglong2*)(xw + 0) = make_ulonglong2(pk2(xr0, xr0), pk2(xr1, xr1));
            *(ulonglong2*)(xw + 2) = make_ulonglong2(pk2(xr2, xr2), pk2(xr3, xr3));
        }

        // ---- per-warp poll: producer CTA `ks` only (fused tag+data) ----
        {
            ull* sp = ht + ((size_t)par * HID + kown) * BG;
            const unsigned tg = (unsigned)t;
            ull v0 = ld_rlx(sp + 0), v1 = ld_rlx(sp + 1);
            ull v2 = ld_rlx(sp + 2), v3 = ld_rlx(sp + 3);
            while (((unsigned)(v0 >> 32) != tg) | ((unsigned)(v1 >> 32) != tg) |
                   ((unsigned)(v2 >> 32) != tg) | ((unsigned)(v3 >> 32) != tg)) {
                v0 = ld_rlx(sp + 0); v1 = ld_rlx(sp + 1);
                v2 = ld_rlx(sp + 2); v3 = ld_rlx(sp + 3);
            }
            float h0 = __uint_as_float((unsigned)v0);
            float h1 = __uint_as_float((unsigned)v1);
            float h2 = __uint_as_float((unsigned)v2);
            float h3 = __uint_as_float((unsigned)v3);
            ull* hw = hd + (size_t)kown * BG;
            *(ulonglong2*)(hw + 0) = make_ulonglong2(pk2(h0, h0), pk2(h1, h1));
            *(ulonglong2*)(hw + 2) = make_ulonglong2(pk2(h2, h2), pk2(h3, h3));
        }
        __syncwarp();   // cross-lane hd visibility inside this warp

        // ---- h-GEMM chunk (own K-split; accumulates onto xp-partials) ----
        {
            const ull* hp = hd + (size_t)(ks * 32) * BG;
#pragma unroll
            for (int kk = 0; kk < 32; kk++) {
                ulonglong2 d0 = *(const ulonglong2*)(hp + kk * 4);
                ulonglong2 d1 = *(const ulonglong2*)(hp + kk * 4 + 2);
                a00 = ffma2(d0.x, wA[kk], a00); a01 = ffma2(d0.x, wB[kk], a01);
                a10 = ffma2(d0.y, wA[kk], a10); a11 = ffma2(d0.y, wB[kk], a11);
                a20 = ffma2(d1.x, wA[kk], a20); a21 = ffma2(d1.x, wB[kk], a21);
                a30 = ffma2(d1.y, wA[kk], a30); a31 = ffma2(d1.y, wB[kk], a31);
            }
        }
        {   // stage packed partials (no unpacking movs)
            ulonglong2* rp = red_u + (size_t)par * 4 * 256;
            rp[0 * 256 + tid] = make_ulonglong2(a00, a01);
            rp[1 * 256 + tid] = make_ulonglong2(a10, a11);
            rp[2 * 256 + tid] = make_ulonglong2(a20, a21);
            rp[3 * 256 + tid] = make_ulonglong2(a30, a31);
        }
        __syncthreads();   // the ONE CTA-wide sync per step

        // ---- reduce (f32x2) + act + publish (warps 0-3) ----
        if (tid < 128) {
            const ulonglong2* rp = red_u + ((size_t)par * 4 + rb) * 256;
            ull s0 = biasA, s1 = biasB;
#pragma unroll
            for (int j = 0; j < 8; j++) {
                ulonglong2 v = rp[j * 32 + rc];
                s0 = fadd2(s0, v.x);
                s1 = fadd2(s1, v.y);
            }
            float g0, g1, g2, g3;
            upk2(s0, g0, g1); upk2(s1, g2, g3);
            *(float4*)&gates_s[rb * 128 + 4 * rc] = make_float4(g0, g1, g2, g3);
        }
        __syncwarp();
        if (tid < 128) {
            float gi = gates_s[rb * 128 +       rc];
            float gf = gates_s[rb * 128 +  32 + rc];
            float gg = gates_s[rb * 128 +  64 + rc];
            float go = gates_s[rb * 128 +  96 + rc];
            float i_ = fsig(gi), f_ = fsig(gf), g_ = ftanh(gg), o_ = fsig(go);
            cstate = f_ * cstate + i_ * g_;
            float h_ = o_ * ftanh(cstate);
            hlast = h_;
            const int kidx = 32 * r + rc;
            ull pv = (ull)__float_as_uint(h_) | ((ull)(unsigned)(t + 1) << 32);
            st_rlx(ht + ((size_t)(par ^ 1) * HID + kidx) * BG + rb, pv);
            out[((size_t)(batch0 + rb) * SEQ + t) * HID + kidx] = h_;
        }

        // ---- prefetch x(t+2) ----
        {
            size_t tn = (size_t)((t + 2 < SEQ) ? (t + 2) : t) * FEAT;
            xr0 = xp0[tn + 0 * (size_t)SEQ * FEAT];
            xr1 = xp0[tn + 1 * (size_t)SEQ * FEAT];
            xr2 = xp0[tn + 2 * (size_t)SEQ * FEAT];
            xr3 = xp0[tn + 3 * (size_t)SEQ * FEAT];
        }

        // ---- xp-GEMM(t+1): fills the publish->poll window ----
        a00 = a01 = a10 = a11 = a20 = a21 = a30 = a31 = pk2(0.f, 0.f);
        {
            const ull* xp_ = xd + ((size_t)(par ^ 1) * HID + ks * 32) * BG;
            const ulonglong2* wp = wx_s + (size_t)(ks * 32) * 32 + cq;
#pragma unroll
            for (int kk = 0; kk < 32; kk++) {
                ulonglong2 d0 = *(const ulonglong2*)(xp_ + kk * 4);
                ulonglong2 d1 = *(const ulonglong2*)(xp_ + kk * 4 + 2);
                ulonglong2 w2 = wp[kk * 32];
                a00 = ffma2(d0.x, w2.x, a00); a01 = ffma2(d0.x, w2.y, a01);
                a10 = ffma2(d0.y, w2.x, a10); a11 = ffma2(d0.y, w2.y, a11);
                a20 = ffma2(d1.x, w2.x, a20); a21 = ffma2(d1.x, w2.y, a21);
                a30 = ffma2(d1.y, w2.x, a30); a31 = ffma2(d1.y, w2.y, a31);
            }
        }
        // no trailing barrier
    }

    // ---- h_n (second output region) ----
    if (tid < 128 && out_size >= (long long)BATCH * SEQ * HID + BATCH * HID) {
        out[(size_t)BATCH * SEQ * HID + (size_t)(batch0 + rb) * HID + 32 * r + rc] = hlast;
    }
}

// ============================================================
extern "C" void kernel_launch(void* const* d_in, const int* in_sizes, int n_in,
                              void* d_out, int out_size)
{
    const float* x  = (const float*)d_in[0];
    const float* WX = (const float*)d_in[1];
    const float* WH = (const float*)d_in[2];
    const float* BX = (const float*)d_in[3];
    const float* BH = (const float*)d_in[4];
    float* out = (float*)d_out;

    const size_t smem_bytes = 131072 + 8192 + 16384 + 32768 + 2048;  // 190464
    cudaFuncSetAttribute(lstm_kernel, cudaFuncAttributeMaxDynamicSharedMemorySize,
                         (int)smem_bytes);

    init_kernel<<<64, 256>>>();
    lstm_kernel<<<NGROUP * NCTA_PG, 256, smem_bytes>>>(
        out, x, WX, WH, BX, BH, (long long)out_size);
}

// round 8
// speedup vs baseline: 1.3430x; 1.0143x over previous
#include <cuda_runtime.h>
#include <stdint.h>

typedef unsigned long long ull;

// ---------- f32x2 packed-fp32 helpers ----------
__device__ __forceinline__ ull pk2(float lo, float hi) {
    ull r; asm("mov.b64 %0,{%1,%2};" : "=l"(r) : "f"(lo), "f"(hi)); return r;
}
__device__ __forceinline__ void upk2(ull v, float& lo, float& hi) {
    asm("mov.b64 {%0,%1},%2;" : "=f"(lo), "=f"(hi) : "l"(v));
}
__device__ __forceinline__ ull ffma2(ull a, ull b, ull c) {
    ull d; asm("fma.rn.f32x2 %0,%1,%2,%3;" : "=l"(d) : "l"(a), "l"(b), "l"(c)); return d;
}
__device__ __forceinline__ ull fadd2(ull a, ull b) {
    ull d; asm("add.rn.f32x2 %0,%1,%2;" : "=l"(d) : "l"(a), "l"(b)); return d;
}

// ---------- relaxed 64-bit L2 atoms (tag+data fused in one word) ----------
__device__ __forceinline__ ull ld_rlx(const ull* p) {
    ull v;
    asm volatile("ld.relaxed.gpu.global.u64 %0, [%1];" : "=l"(v) : "l"(p) : "memory");
    return v;
}
__device__ __forceinline__ void st_rlx(ull* p, ull v) {
    asm volatile("st.relaxed.gpu.global.u64 [%0], %1;" :: "l"(p), "l"(v) : "memory");
}

// ---------- problem constants ----------
#define BATCH   64
#define SEQ     2048
#define FEAT    256
#define HID     256
#define G4      1024           // 4*HID
#define BG      4              // batches per group
#define NCTA_PG 8              // CTAs per group
#define NGROUP  16

// ---------- scratch ----------
__device__ ull ht_buf[NGROUP * 2 * HID * BG];   // tagged h: lo=h bits, hi=step tag

// ============================================================
__global__ void init_kernel() {
    int t = blockIdx.x * blockDim.x + threadIdx.x;
    if (t < NGROUP * HID * BG) {
        int grp = t / (HID * BG);
        int rem = t % (HID * BG);
        ht_buf[(size_t)grp * 2 * HID * BG + rem] = 0ull;   // parity-0: tag 0, h=0
    }
}

// ============================================================
// Fused LSTM: 16 groups x 8 CTAs. gates(t)=[x(t),h(t)]@[WX;WH].
// WH slice in 128 regs/thread; WX pre-packed in SMEM.
// Warp w's K-split == producer CTA w; per-warp poll of fused
// tag+data words, NO CTA-wide poll barrier (red_u parity-buffered).
// NEW (R8): the poll loads for step t+1 are issued SPECULATIVELY
// in the middle of xp-GEMM(t+1); the top-of-loop check is then a
// register compare — the L2 round trip rides under the GEMM.
// ============================================================
__device__ __forceinline__ float fsig(float x) {
    return __fdividef(1.0f, 1.0f + __expf(-x));
}
__device__ __forceinline__ float ftanh(float x) { return 2.0f * fsig(2.0f * x) - 1.0f; }

__global__ __launch_bounds__(256, 1)
void lstm_kernel(float* __restrict__ out,
                 const float* __restrict__ x,
                 const float* __restrict__ WX,
                 const float* __restrict__ WH,
                 const float* __restrict__ BX,
                 const float* __restrict__ BH,
                 long long out_size)
{
    extern __shared__ char smem[];
    ulonglong2* wx_s    = (ulonglong2*)smem;                         // [256][32]      128 KB
    ull*        hd      = (ull*)(smem + 131072);                     // [256][4]         8 KB
    ull*        xd      = (ull*)(smem + 131072 + 8192);              // [2][256][4]     16 KB
    ulonglong2* red_u   = (ulonglong2*)(smem + 131072 + 8192 + 16384);  // [2][4][256]  32 KB
    float*      gates_s = (float*)(smem + 131072 + 8192 + 16384 + 32768); // [4][128]    2 KB

    const int tid = threadIdx.x;
    const int grp = blockIdx.x >> 3;
    const int r   = blockIdx.x & 7;
    const int batch0 = grp * BG;

    const int ks   = tid >> 5;           // K-split warp id == producer CTA id
    const int lane = tid & 31;
    const int cq   = lane;               // col-quad (local cols 4cq..4cq+3)
    const int rb   = tid >> 5;           // act/reduce batch (tid<128)
    const int rc   = lane;               // act hidden unit / reducer col-quad
    const int kown = 32 * ks + lane;     // the k-slot this thread polls/packs

    // ---- load WX slice into SMEM, pre-packed (wA,wB) ----
    for (int idx = tid; idx < 256 * 32; idx += 256) {
        int f = idx >> 5, ci = idx & 31;
        int gc = (ci >> 3) * HID + 32 * r + ((4 * ci) & 31);
        float4 w4 = *(const float4*)&WX[(size_t)f * G4 + gc];
        wx_s[idx] = make_ulonglong2(pk2(w4.x, w4.y), pk2(w4.z, w4.w));
    }

    // ---- load WH slice into registers ----
    ull wA[32], wB[32];
    {
        const int gc = (cq >> 3) * HID + 32 * r + ((4 * cq) & 31);
        const float* wp = WH + (size_t)(32 * ks) * G4 + gc;
#pragma unroll
        for (int kk = 0; kk < 32; kk++) {
            float4 w4 = *(const float4*)(wp + (size_t)kk * G4);
            wA[kk] = pk2(w4.x, w4.y);
            wB[kk] = pk2(w4.z, w4.w);
        }
    }

    // ---- bias, packed f32x2 (folded once) ----
    ull biasA = pk2(0.f, 0.f), biasB = biasA;
    if (tid < 128) {
        int gc = (rc >> 3) * HID + 32 * r + ((4 * rc) & 31);
        float4 bx4 = *(const float4*)&BX[gc];
        float4 bh4 = *(const float4*)&BH[gc];
        biasA = pk2(bx4.x + bh4.x, bx4.y + bh4.y);
        biasB = pk2(bx4.z + bh4.z, bx4.w + bh4.w);
    }

    // ---- x prefetch: thread owns feat=tid, 4 batches ----
    const float* xp0 = x + (size_t)batch0 * SEQ * FEAT + tid;
    float xr0, xr1, xr2, xr3;
    {   // x(0) -> xd[0]
        float a0 = xp0[0 * (size_t)SEQ * FEAT];
        float a1 = xp0[1 * (size_t)SEQ * FEAT];
        float a2 = xp0[2 * (size_t)SEQ * FEAT];
        float a3 = xp0[3 * (size_t)SEQ * FEAT];
        ull* xw = xd + (size_t)tid * BG;
        *(ulonglong2*)(xw + 0) = make_ulonglong2(pk2(a0, a0), pk2(a1, a1));
        *(ulonglong2*)(xw + 2) = make_ulonglong2(pk2(a2, a2), pk2(a3, a3));
    }
    xr0 = xp0[(size_t)1 * FEAT + 0 * (size_t)SEQ * FEAT];
    xr1 = xp0[(size_t)1 * FEAT + 1 * (size_t)SEQ * FEAT];
    xr2 = xp0[(size_t)1 * FEAT + 2 * (size_t)SEQ * FEAT];
    xr3 = xp0[(size_t)1 * FEAT + 3 * (size_t)SEQ * FEAT];

    __syncthreads();   // wx_s + xd[0] visible

    ull* ht = &ht_buf[(size_t)grp * 2 * HID * BG];   // [parity][k][b]

    ull a00, a01, a10, a11, a20, a21, a30, a31;

    // ---- prologue: xp-GEMM(0) ----
    a00 = a01 = a10 = a11 = a20 = a21 = a30 = a31 = pk2(0.f, 0.f);
    {
        const ull* xp_ = xd + (size_t)(ks * 32) * BG;
        const ulonglong2* wp = wx_s + (size_t)(ks * 32) * 32 + cq;
#pragma unroll
        for (int kk = 0; kk < 32; kk++) {
            ulonglong2 d0 = *(const ulonglong2*)(xp_ + kk * 4);
            ulonglong2 d1 = *(const ulonglong2*)(xp_ + kk * 4 + 2);
            ulonglong2 w2 = wp[kk * 32];
            a00 = ffma2(d0.x, w2.x, a00); a01 = ffma2(d0.x, w2.y, a01);
            a10 = ffma2(d0.y, w2.x, a10); a11 = ffma2(d0.y, w2.y, a11);
            a20 = ffma2(d1.x, w2.x, a20); a21 = ffma2(d1.x, w2.y, a21);
            a30 = ffma2(d1.y, w2.x, a30); a31 = ffma2(d1.y, w2.y, a31);
        }
    }

    // ---- speculative preload for t=0 (parity 0, tag 0 — init guarantees hit) ----
    ull sv0, sv1, sv2, sv3;
    {
        const ull* sp = ht + (size_t)kown * BG;
        sv0 = ld_rlx(sp + 0); sv1 = ld_rlx(sp + 1);
        sv2 = ld_rlx(sp + 2); sv3 = ld_rlx(sp + 3);
    }

    float cstate = 0.0f, hlast = 0.0f;

    for (int t = 0; t < SEQ; t++) {
        const int par = t & 1;

        // ---- stage x(t+1) -> xd[par^1] (fire-and-forget STS) ----
        {
            ull* xw = xd + ((size_t)(par ^ 1) * HID + tid) * BG;
            *(ulonglong2*)(xw + 0) = make_ulonglong2(pk2(xr0, xr0), pk2(xr1, xr1));
            *(ulonglong2*)(xw + 2) = make_ulonglong2(pk2(xr2, xr2), pk2(xr3, xr3));
        }

        // ---- check speculative poll values; re-poll only on miss ----
        {
            const ull* sp = ht + ((size_t)par * HID + kown) * BG;
            const unsigned tg = (unsigned)t;
            while (((unsigned)(sv0 >> 32) != tg) | ((unsigned)(sv1 >> 32) != tg) |
                   ((unsigned)(sv2 >> 32) != tg) | ((unsigned)(sv3 >> 32) != tg)) {
                sv0 = ld_rlx(sp + 0); sv1 = ld_rlx(sp + 1);
                sv2 = ld_rlx(sp + 2); sv3 = ld_rlx(sp + 3);
            }
            float h0 = __uint_as_float((unsigned)sv0);
            float h1 = __uint_as_float((unsigned)sv1);
            float h2 = __uint_as_float((unsigned)sv2);
            float h3 = __uint_as_float((unsigned)sv3);
            ull* hw = hd + (size_t)kown * BG;
            *(ulonglong2*)(hw + 0) = make_ulonglong2(pk2(h0, h0), pk2(h1, h1));
            *(ulonglong2*)(hw + 2) = make_ulonglong2(pk2(h2, h2), pk2(h3, h3));
        }
        __syncwarp();   // cross-lane hd visibility inside this warp

        // ---- h-GEMM chunk (own K-split; accumulates onto xp-partials) ----
        {
            const ull* hp = hd + (size_t)(ks * 32) * BG;
#pragma unroll
            for (int kk = 0; kk < 32; kk++) {
                ulonglong2 d0 = *(const ulonglong2*)(hp + kk * 4);
                ulonglong2 d1 = *(const ulonglong2*)(hp + kk * 4 + 2);
                a00 = ffma2(d0.x, wA[kk], a00); a01 = ffma2(d0.x, wB[kk], a01);
                a10 = ffma2(d0.y, wA[kk], a10); a11 = ffma2(d0.y, wB[kk], a11);
                a20 = ffma2(d1.x, wA[kk], a20); a21 = ffma2(d1.x, wB[kk], a21);
                a30 = ffma2(d1.y, wA[kk], a30); a31 = ffma2(d1.y, wB[kk], a31);
            }
        }
        {   // stage packed partials
            ulonglong2* rp = red_u + (size_t)par * 4 * 256;
            rp[0 * 256 + tid] = make_ulonglong2(a00, a01);
            rp[1 * 256 + tid] = make_ulonglong2(a10, a11);
            rp[2 * 256 + tid] = make_ulonglong2(a20, a21);
            rp[3 * 256 + tid] = make_ulonglong2(a30, a31);
        }
        __syncthreads();   // the ONE CTA-wide sync per step

        // ---- reduce (f32x2) + act + publish (warps 0-3) ----
        if (tid < 128) {
            const ulonglong2* rp = red_u + ((size_t)par * 4 + rb) * 256;
            ull s0 = biasA, s1 = biasB;
#pragma unroll
            for (int j = 0; j < 8; j++) {
                ulonglong2 v = rp[j * 32 + rc];
                s0 = fadd2(s0, v.x);
                s1 = fadd2(s1, v.y);
            }
            float g0, g1, g2, g3;
            upk2(s0, g0, g1); upk2(s1, g2, g3);
            *(float4*)&gates_s[rb * 128 + 4 * rc] = make_float4(g0, g1, g2, g3);
        }
        __syncwarp();
        if (tid < 128) {
            float gi = gates_s[rb * 128 +       rc];
            float gf = gates_s[rb * 128 +  32 + rc];
            float gg = gates_s[rb * 128 +  64 + rc];
            float go = gates_s[rb * 128 +  96 + rc];
            float i_ = fsig(gi), f_ = fsig(gf), g_ = ftanh(gg), o_ = fsig(go);
            cstate = f_ * cstate + i_ * g_;
            float h_ = o_ * ftanh(cstate);
            hlast = h_;
            const int kidx = 32 * r + rc;
            ull pv = (ull)__float_as_uint(h_) | ((ull)(unsigned)(t + 1) << 32);
            st_rlx(ht + ((size_t)(par ^ 1) * HID + kidx) * BG + rb, pv);
            out[((size_t)(batch0 + rb) * SEQ + t) * HID + kidx] = h_;
        }

        // ---- prefetch x(t+2) ----
        {
            size_t tn = (size_t)((t + 2 < SEQ) ? (t + 2) : t) * FEAT;
            xr0 = xp0[tn + 0 * (size_t)SEQ * FEAT];
            xr1 = xp0[tn + 1 * (size_t)SEQ * FEAT];
            xr2 = xp0[tn + 2 * (size_t)SEQ * FEAT];
            xr3 = xp0[tn + 3 * (size_t)SEQ * FEAT];
        }

        // ---- xp-GEMM(t+1), with speculative polls for t+1 at midpoint ----
        a00 = a01 = a10 = a11 = a20 = a21 = a30 = a31 = pk2(0.f, 0.f);
        {
            const ull* xp_ = xd + ((size_t)(par ^ 1) * HID + ks * 32) * BG;
            const ulonglong2* wp = wx_s + (size_t)(ks * 32) * 32 + cq;
#pragma unroll
            for (int kk = 0; kk < 16; kk++) {
                ulonglong2 d0 = *(const ulonglong2*)(xp_ + kk * 4);
                ulonglong2 d1 = *(const ulonglong2*)(xp_ + kk * 4 + 2);
                ulonglong2 w2 = wp[kk * 32];
                a00 = ffma2(d0.x, w2.x, a00); a01 = ffma2(d0.x, w2.y, a01);
                a10 = ffma2(d0.y, w2.x, a10); a11 = ffma2(d0.y, w2.y, a11);
                a20 = ffma2(d1.x, w2.x, a20); a21 = ffma2(d1.x, w2.y, a21);
                a30 = ffma2(d1.y, w2.x, a30); a31 = ffma2(d1.y, w2.y, a31);
            }
            // ---- speculative poll issue for step t+1 (rides under GEMM tail) ----
            {
                const ull* sp = ht + ((size_t)(par ^ 1) * HID + kown) * BG;
                sv0 = ld_rlx(sp + 0); sv1 = ld_rlx(sp + 1);
                sv2 = ld_rlx(sp + 2); sv3 = ld_rlx(sp + 3);
            }
#pragma unroll
            for (int kk = 16; kk < 32; kk++) {
                ulonglong2 d0 = *(const ulonglong2*)(xp_ + kk * 4);
                ulonglong2 d1 = *(const ulonglong2*)(xp_ + kk * 4 + 2);
                ulonglong2 w2 = wp[kk * 32];
                a00 = ffma2(d0.x, w2.x, a00); a01 = ffma2(d0.x, w2.y, a01);
                a10 = ffma2(d0.y, w2.x, a10); a11 = ffma2(d0.y, w2.y, a11);
                a20 = ffma2(d1.x, w2.x, a20); a21 = ffma2(d1.x, w2.y, a21);
                a30 = ffma2(d1.y, w2.x, a30); a31 = ffma2(d1.y, w2.y, a31);
            }
        }
        // no trailing barrier
    }

    // ---- h_n (second output region) ----
    if (tid < 128 && out_size >= (long long)BATCH * SEQ * HID + BATCH * HID) {
        out[(size_t)BATCH * SEQ * HID + (size_t)(batch0 + rb) * HID + 32 * r + rc] = hlast;
    }
}

// ============================================================
extern "C" void kernel_launch(void* const* d_in, const int* in_sizes, int n_in,
                              void* d_out, int out_size)
{
    const float* x  = (const float*)d_in[0];
    const float* WX = (const float*)d_in[1];
    const float* WH = (const float*)d_in[2];
    const float* BX = (const float*)d_in[3];
    const float* BH = (const float*)d_in[4];
    float* out = (float*)d_out;

    const size_t smem_bytes = 131072 + 8192 + 16384 + 32768 + 2048;  // 190464
    cudaFuncSetAttribute(lstm_kernel, cudaFuncAttributeMaxDynamicSharedMemorySize,
                         (int)smem_bytes);

    init_kernel<<<64, 256>>>();
    lstm_kernel<<<NGROUP * NCTA_PG, 256, smem_bytes>>>(
        out, x, WX, WH, BX, BH, (long long)out_size);
}

// round 9
// speedup vs baseline: 1.4125x; 1.0518x over previous
#include <cuda_runtime.h>
#include <stdint.h>

typedef unsigned long long ull;

// ---------- f32x2 packed-fp32 helpers ----------
__device__ __forceinline__ ull pk2(float lo, float hi) {
    ull r; asm("mov.b64 %0,{%1,%2};" : "=l"(r) : "f"(lo), "f"(hi)); return r;
}
__device__ __forceinline__ void upk2(ull v, float& lo, float& hi) {
    asm("mov.b64 {%0,%1},%2;" : "=f"(lo), "=f"(hi) : "l"(v));
}
__device__ __forceinline__ ull ffma2(ull a, ull b, ull c) {
    ull d; asm("fma.rn.f32x2 %0,%1,%2,%3;" : "=l"(d) : "l"(a), "l"(b), "l"(c)); return d;
}
__device__ __forceinline__ ull fadd2(ull a, ull b) {
    ull d; asm("add.rn.f32x2 %0,%1,%2;" : "=l"(d) : "l"(a), "l"(b)); return d;
}

// ---------- L2 sync primitives ----------
__device__ __forceinline__ ull ld_rlx(const ull* p) {
    ull v;
    asm volatile("ld.relaxed.gpu.global.u64 %0, [%1];" : "=l"(v) : "l"(p) : "memory");
    return v;
}
__device__ __forceinline__ void st_rlx(ull* p, ull v) {
    asm volatile("st.relaxed.gpu.global.u64 [%0], %1;" :: "l"(p), "l"(v) : "memory");
}
__device__ __forceinline__ unsigned ld_acq_u32(const unsigned* p) {
    unsigned v;
    asm volatile("ld.acquire.gpu.global.u32 %0, [%1];" : "=r"(v) : "l"(p) : "memory");
    return v;
}
__device__ __forceinline__ void st_rel_u32(unsigned* p, unsigned v) {
    asm volatile("st.release.gpu.global.u32 [%0], %1;" :: "l"(p), "r"(v) : "memory");
}

// ---------- problem constants ----------
#define BATCH   64
#define SEQ     2048
#define FEAT    256
#define HID     256
#define G4      1024
#define BG      4
#define NCTA_PG 8
#define NGROUP  16
#define NWORK   128
#define NHELP   20

// ---------- scratch ----------
__device__ ull      ht_buf[NGROUP * 2 * BG * HID];          // tagged h [grp][par][b][k]
__device__ float    xp_part[(size_t)SEQ * BATCH * G4];      // 512MB helper partials [t][b][col]
__device__ unsigned flag_buf[SEQ];                          // per-t ready flags

// ============================================================
__global__ void init_kernel() {
    int t = blockIdx.x * blockDim.x + threadIdx.x;
    if (t < NGROUP * 1024) {                 // zero parity-0 slots (tag 0, h=0)
        int grp = t >> 10, rem = t & 1023;
        ht_buf[grp * 2048 + rem] = 0ull;
    }
    if (t < SEQ) flag_buf[t] = 0u;
}

// ============================================================
// Helper body: 20 CTAs precompute xp_part over offloaded K set
// offK = [64,96) U [192,224)  (worker warps 2 and 6).
// Helper j handles t = j, j+20, j+40, ...  Flag per t (release).
// ============================================================
__device__ void helper_body(int hj, const float* __restrict__ x,
                            const float* __restrict__ WX, char* smem)
{
    float (*xs)[68] = (float(*)[68])smem;                  // [64k][64b pad]  17.4KB
    float (*ws)[64] = (float(*)[64])(smem + 64 * 68 * 4);  // [64k][64c]      16.4KB

    const int tid = threadIdx.x;
    const int ty = tid >> 4, tx = tid & 15;

    for (int t = hj; t < SEQ; t += NHELP) {
        // ---- stage x-tile: 64 batches x 64 offK feats ----
#pragma unroll
        for (int it = 0; it < 4; it++) {
            int f = tid + 256 * it;            // 0..1023 float4 units
            int row = f >> 4, j = f & 15;
            int kg = (j < 8) ? (64 + 4 * j) : (192 + 4 * (j - 8));
            float4 v = *(const float4*)&x[((size_t)row * SEQ + t) * FEAT + kg];
            int kl = 4 * j;
            xs[kl + 0][row] = v.x; xs[kl + 1][row] = v.y;
            xs[kl + 2][row] = v.z; xs[kl + 3][row] = v.w;
        }
        for (int ct = 0; ct < 16; ct++) {
            __syncthreads();     // xs ready / prior compute done with ws
#pragma unroll
            for (int it = 0; it < 4; it++) {
                int f2 = tid + 256 * it;       // 0..1023: k = f2>>4, c4 = f2&15
                int k = f2 >> 4, c4 = f2 & 15;
                int kg = (k < 32) ? (64 + k) : (192 + (k - 32));
                float4 v = *(const float4*)&WX[(size_t)kg * G4 + 64 * ct + 4 * c4];
                *(float4*)&ws[k][4 * c4] = v;
            }
            __syncthreads();
            ull acc[4][2];
#pragma unroll
            for (int i = 0; i < 4; i++) { acc[i][0] = pk2(0.f, 0.f); acc[i][1] = pk2(0.f, 0.f); }
#pragma unroll 16
            for (int kk = 0; kk < 64; kk++) {
                float4 a4 = *(const float4*)&xs[kk][4 * ty];
                float4 b4 = *(const float4*)&ws[kk][4 * tx];
                ull b01 = pk2(b4.x, b4.y), b23 = pk2(b4.z, b4.w);
                ull am;
                am = pk2(a4.x, a4.x); acc[0][0] = ffma2(am, b01, acc[0][0]); acc[0][1] = ffma2(am, b23, acc[0][1]);
                am = pk2(a4.y, a4.y); acc[1][0] = ffma2(am, b01, acc[1][0]); acc[1][1] = ffma2(am, b23, acc[1][1]);
                am = pk2(a4.z, a4.z); acc[2][0] = ffma2(am, b01, acc[2][0]); acc[2][1] = ffma2(am, b23, acc[2][1]);
                am = pk2(a4.w, a4.w); acc[3][0] = ffma2(am, b01, acc[3][0]); acc[3][1] = ffma2(am, b23, acc[3][1]);
            }
            size_t base = ((size_t)t * BATCH + 4 * ty) * G4 + 64 * ct + 4 * tx;
#pragma unroll
            for (int i = 0; i < 4; i++) {
                float4 o;
                upk2(acc[i][0], o.x, o.y);
                upk2(acc[i][1], o.z, o.w);
                *(float4*)&xp_part[base + (size_t)i * G4] = o;
            }
        }
        __syncthreads();         // all STGs done before flag
        if (tid == 0) st_rel_u32(&flag_buf[t], 1u);
        __syncthreads();         // before xs overwrite next t
    }
}

// ============================================================
// Worker body: 128 CTAs, same structure as R8 except:
//  - warps {2,6} skip their xp-GEMM chunk (precomputed by helpers)
//  - reducers add xp_part (prefetched under h-GEMM, flag-gated)
//  - ht_buf relayout [par][b][k]: coalesced polls & publishes
// ============================================================
__device__ __forceinline__ float fsig(float x) {
    return __fdividef(1.0f, 1.0f + __expf(-x));
}
__device__ __forceinline__ float ftanh(float x) { return 2.0f * fsig(2.0f * x) - 1.0f; }

__device__ void worker_body(float* __restrict__ out,
                            const float* __restrict__ x,
                            const float* __restrict__ WX,
                            const float* __restrict__ WH,
                            const float* __restrict__ BX,
                            const float* __restrict__ BH,
                            long long out_size, char* smem)
{
    ulonglong2* wx_s    = (ulonglong2*)smem;                          // 128 KB
    ull*        hd      = (ull*)(smem + 131072);                      // [256][4]  8 KB
    ull*        xd      = (ull*)(smem + 131072 + 8192);               // [2][256][4] 16 KB
    ulonglong2* red_u   = (ulonglong2*)(smem + 131072 + 8192 + 16384);   // [2][4][256] 32 KB
    float*      gates_s = (float*)(smem + 131072 + 8192 + 16384 + 32768); // [4][128] 2 KB

    const int tid = threadIdx.x;
    const int grp = blockIdx.x >> 3;
    const int r   = blockIdx.x & 7;
    const int batch0 = grp * BG;

    const int ks   = tid >> 5;
    const int lane = tid & 31;
    const int cq   = lane;
    const int rb   = tid >> 5;
    const int rc   = lane;
    const int kown = 32 * ks + lane;
    const bool xact = (ks != 2 && ks != 6);   // warps 2,6 offloaded to helpers

    // ---- load WX slice into SMEM, pre-packed ----
    for (int idx = tid; idx < 256 * 32; idx += 256) {
        int f = idx >> 5, ci = idx & 31;
        int gc = (ci >> 3) * HID + 32 * r + ((4 * ci) & 31);
        float4 w4 = *(const float4*)&WX[(size_t)f * G4 + gc];
        wx_s[idx] = make_ulonglong2(pk2(w4.x, w4.y), pk2(w4.z, w4.w));
    }

    // ---- WH slice into registers ----
    ull wA[32], wB[32];
    {
        const int gc = (cq >> 3) * HID + 32 * r + ((4 * cq) & 31);
        const float* wp = WH + (size_t)(32 * ks) * G4 + gc;
#pragma unroll
        for (int kk = 0; kk < 32; kk++) {
            float4 w4 = *(const float4*)(wp + (size_t)kk * G4);
            wA[kk] = pk2(w4.x, w4.y);
            wB[kk] = pk2(w4.z, w4.w);
        }
    }

    // ---- bias + xp_part column for reducers ----
    ull biasA = pk2(0.f, 0.f), biasB = biasA;
    int gcol = 0;
    if (tid < 128) {
        gcol = (rc >> 3) * HID + 32 * r + ((4 * rc) & 31);
        float4 bx4 = *(const float4*)&BX[gcol];
        float4 bh4 = *(const float4*)&BH[gcol];
        biasA = pk2(bx4.x + bh4.x, bx4.y + bh4.y);
        biasB = pk2(bx4.z + bh4.z, bx4.w + bh4.w);
    }

    // ---- x prefetch (only warps that run xp) ----
    const float* xp0 = x + (size_t)batch0 * SEQ * FEAT + tid;
    float xr0 = 0.f, xr1 = 0.f, xr2 = 0.f, xr3 = 0.f;
    if (xact) {
        float a0 = xp0[0 * (size_t)SEQ * FEAT];
        float a1 = xp0[1 * (size_t)SEQ * FEAT];
        float a2 = xp0[2 * (size_t)SEQ * FEAT];
        float a3 = xp0[3 * (size_t)SEQ * FEAT];
        ull* xw = xd + (size_t)tid * BG;
        *(ulonglong2*)(xw + 0) = make_ulonglong2(pk2(a0, a0), pk2(a1, a1));
        *(ulonglong2*)(xw + 2) = make_ulonglong2(pk2(a2, a2), pk2(a3, a3));
        xr0 = xp0[(size_t)1 * FEAT + 0 * (size_t)SEQ * FEAT];
        xr1 = xp0[(size_t)1 * FEAT + 1 * (size_t)SEQ * FEAT];
        xr2 = xp0[(size_t)1 * FEAT + 2 * (size_t)SEQ * FEAT];
        xr3 = xp0[(size_t)1 * FEAT + 3 * (size_t)SEQ * FEAT];
    }
    __syncthreads();

    ull* htg = &ht_buf[(size_t)grp * 2048];   // [par(1024)][b(256)][k]

    ull a00, a01, a10, a11, a20, a21, a30, a31;
    a00 = a01 = a10 = a11 = a20 = a21 = a30 = a31 = pk2(0.f, 0.f);
    if (xact) {   // prologue xp-GEMM(0)
        const ull* xp_ = xd + (size_t)(ks * 32) * BG;
        const ulonglong2* wp = wx_s + (size_t)(ks * 32) * 32 + cq;
#pragma unroll
        for (int kk = 0; kk < 32; kk++) {
            ulonglong2 d0 = *(const ulonglong2*)(xp_ + kk * 4);
            ulonglong2 d1 = *(const ulonglong2*)(xp_ + kk * 4 + 2);
            ulonglong2 w2 = wp[kk * 32];
            a00 = ffma2(d0.x, w2.x, a00); a01 = ffma2(d0.x, w2.y, a01);
            a10 = ffma2(d0.y, w2.x, a10); a11 = ffma2(d0.y, w2.y, a11);
            a20 = ffma2(d1.x, w2.x, a20); a21 = ffma2(d1.x, w2.y, a21);
            a30 = ffma2(d1.y, w2.x, a30); a31 = ffma2(d1.y, w2.y, a31);
        }
    }

    // ---- speculative preload for t=0 (parity 0, tag 0) ----
    ull sv0, sv1, sv2, sv3;
    {
        const ull* sp = htg + kown;
        sv0 = ld_rlx(sp + 0 * 256); sv1 = ld_rlx(sp + 1 * 256);
        sv2 = ld_rlx(sp + 2 * 256); sv3 = ld_rlx(sp + 3 * 256);
    }

    float cstate = 0.0f, hlast = 0.0f;

    for (int t = 0; t < SEQ; t++) {
        const int par = t & 1;

        // ---- stage x(t+1) ----
        if (xact) {
            ull* xw = xd + ((size_t)(par ^ 1) * HID + tid) * BG;
            *(ulonglong2*)(xw + 0) = make_ulonglong2(pk2(xr0, xr0), pk2(xr1, xr1));
            *(ulonglong2*)(xw + 2) = make_ulonglong2(pk2(xr2, xr2), pk2(xr3, xr3));
        }

        // ---- check speculative polls; re-poll on miss ----
        {
            const ull* sp = htg + (size_t)par * 1024 + kown;
            const unsigned tg = (unsigned)t;
            while (((unsigned)(sv0 >> 32) != tg) | ((unsigned)(sv1 >> 32) != tg) |
                   ((unsigned)(sv2 >> 32) != tg) | ((unsigned)(sv3 >> 32) != tg)) {
                sv0 = ld_rlx(sp + 0 * 256); sv1 = ld_rlx(sp + 1 * 256);
                sv2 = ld_rlx(sp + 2 * 256); sv3 = ld_rlx(sp + 3 * 256);
            }
            float h0 = __uint_as_float((unsigned)sv0);
            float h1 = __uint_as_float((unsigned)sv1);
            float h2 = __uint_as_float((unsigned)sv2);
            float h3 = __uint_as_float((unsigned)sv3);
            ull* hw = hd + (size_t)kown * BG;
            *(ulonglong2*)(hw + 0) = make_ulonglong2(pk2(h0, h0), pk2(h1, h1));
            *(ulonglong2*)(hw + 2) = make_ulonglong2(pk2(h2, h2), pk2(h3, h3));
        }

        // ---- flag-gated xp_part prefetch (reducers; hides under h-GEMM) ----
        float4 xpp = make_float4(0.f, 0.f, 0.f, 0.f);
        if (tid < 128) {
            while (ld_acq_u32(&flag_buf[t]) == 0u) { }
            xpp = __ldcg((const float4*)&xp_part[((size_t)t * BATCH + batch0 + rb) * G4 + gcol]);
        }
        __syncwarp();

        // ---- h-GEMM chunk ----
        {
            const ull* hp = hd + (size_t)(ks * 32) * BG;
#pragma unroll
            for (int kk = 0; kk < 32; kk++) {
                ulonglong2 d0 = *(const ulonglong2*)(hp + kk * 4);
                ulonglong2 d1 = *(const ulonglong2*)(hp + kk * 4 + 2);
                a00 = ffma2(d0.x, wA[kk], a00); a01 = ffma2(d0.x, wB[kk], a01);
                a10 = ffma2(d0.y, wA[kk], a10); a11 = ffma2(d0.y, wB[kk], a11);
                a20 = ffma2(d1.x, wA[kk], a20); a21 = ffma2(d1.x, wB[kk], a21);
                a30 = ffma2(d1.y, wA[kk], a30); a31 = ffma2(d1.y, wB[kk], a31);
            }
        }
        {
            ulonglong2* rp = red_u + (size_t)par * 4 * 256;
            rp[0 * 256 + tid] = make_ulonglong2(a00, a01);
            rp[1 * 256 + tid] = make_ulonglong2(a10, a11);
            rp[2 * 256 + tid] = make_ulonglong2(a20, a21);
            rp[3 * 256 + tid] = make_ulonglong2(a30, a31);
        }
        __syncthreads();

        // ---- reduce (+bias +xp_part) -> gates -> act -> publish ----
        if (tid < 128) {
            const ulonglong2* rp = red_u + ((size_t)par * 4 + rb) * 256;
            ull s0 = fadd2(biasA, pk2(xpp.x, xpp.y));
            ull s1 = fadd2(biasB, pk2(xpp.z, xpp.w));
#pragma unroll
            for (int j = 0; j < 8; j++) {
                ulonglong2 v = rp[j * 32 + rc];
                s0 = fadd2(s0, v.x);
                s1 = fadd2(s1, v.y);
            }
            float g0, g1, g2, g3;
            upk2(s0, g0, g1); upk2(s1, g2, g3);
            *(float4*)&gates_s[rb * 128 + 4 * rc] = make_float4(g0, g1, g2, g3);
        }
        __syncwarp();
        if (tid < 128) {
            float gi = gates_s[rb * 128 +       rc];
            float gf = gates_s[rb * 128 +  32 + rc];
            float gg = gates_s[rb * 128 +  64 + rc];
            float go = gates_s[rb * 128 +  96 + rc];
            float i_ = fsig(gi), f_ = fsig(gf), g_ = ftanh(gg), o_ = fsig(go);
            cstate = f_ * cstate + i_ * g_;
            float h_ = o_ * ftanh(cstate);
            hlast = h_;
            const int kidx = 32 * r + rc;
            ull pv = (ull)__float_as_uint(h_) | ((ull)(unsigned)(t + 1) << 32);
            st_rlx(htg + (size_t)(par ^ 1) * 1024 + rb * 256 + kidx, pv);   // coalesced
            out[((size_t)(batch0 + rb) * SEQ + t) * HID + kidx] = h_;
        }

        // ---- prefetch x(t+2) ----
        if (xact) {
            size_t tn = (size_t)((t + 2 < SEQ) ? (t + 2) : t) * FEAT;
            xr0 = xp0[tn + 0 * (size_t)SEQ * FEAT];
            xr1 = xp0[tn + 1 * (size_t)SEQ * FEAT];
            xr2 = xp0[tn + 2 * (size_t)SEQ * FEAT];
            xr3 = xp0[tn + 3 * (size_t)SEQ * FEAT];
        }

        // ---- xp-GEMM(t+1) with mid-point speculative polls ----
        a00 = a01 = a10 = a11 = a20 = a21 = a30 = a31 = pk2(0.f, 0.f);
        if (xact) {
            const ull* xp_ = xd + ((size_t)(par ^ 1) * HID + ks * 32) * BG;
            const ulonglong2* wp = wx_s + (size_t)(ks * 32) * 32 + cq;
#pragma unroll
            for (int kk = 0; kk < 16; kk++) {
                ulonglong2 d0 = *(const ulonglong2*)(xp_ + kk * 4);
                ulonglong2 d1 = *(const ulonglong2*)(xp_ + kk * 4 + 2);
                ulonglong2 w2 = wp[kk * 32];
                a00 = ffma2(d0.x, w2.x, a00); a01 = ffma2(d0.x, w2.y, a01);
                a10 = ffma2(d0.y, w2.x, a10); a11 = ffma2(d0.y, w2.y, a11);
                a20 = ffma2(d1.x, w2.x, a20); a21 = ffma2(d1.x, w2.y, a21);
                a30 = ffma2(d1.y, w2.x, a30); a31 = ffma2(d1.y, w2.y, a31);
            }
            {
                const ull* sp = htg + (size_t)(par ^ 1) * 1024 + kown;
                sv0 = ld_rlx(sp + 0 * 256); sv1 = ld_rlx(sp + 1 * 256);
                sv2 = ld_rlx(sp + 2 * 256); sv3 = ld_rlx(sp + 3 * 256);
            }
#pragma unroll
            for (int kk = 16; kk < 32; kk++) {
                ulonglong2 d0 = *(const ulonglong2*)(xp_ + kk * 4);
                ulonglong2 d1 = *(const ulonglong2*)(xp_ + kk * 4 + 2);
                ulonglong2 w2 = wp[kk * 32];
                a00 = ffma2(d0.x, w2.x, a00); a01 = ffma2(d0.x, w2.y, a01);
                a10 = ffma2(d0.y, w2.x, a10); a11 = ffma2(d0.y, w2.y, a11);
                a20 = ffma2(d1.x, w2.x, a20); a21 = ffma2(d1.x, w2.y, a21);
                a30 = ffma2(d1.y, w2.x, a30); a31 = ffma2(d1.y, w2.y, a31);
            }
        } else {
            const ull* sp = htg + (size_t)(par ^ 1) * 1024 + kown;
            sv0 = ld_rlx(sp + 0 * 256); sv1 = ld_rlx(sp + 1 * 256);
            sv2 = ld_rlx(sp + 2 * 256); sv3 = ld_rlx(sp + 3 * 256);
        }
    }

    if (tid < 128 && out_size >= (long long)BATCH * SEQ * HID + BATCH * HID) {
        out[(size_t)BATCH * SEQ * HID + (size_t)(batch0 + rb) * HID + 32 * r + rc] = hlast;
    }
}

// ============================================================
__global__ __launch_bounds__(256, 1)
void lstm_kernel(float* __restrict__ out,
                 const float* __restrict__ x,
                 const float* __restrict__ WX,
                 const float* __restrict__ WH,
                 const float* __restrict__ BX,
                 const float* __restrict__ BH,
                 long long out_size)
{
    extern __shared__ char smem[];
    if (blockIdx.x >= NWORK) {
        helper_body(blockIdx.x - NWORK, x, WX, smem);
    } else {
        worker_body(out, x, WX, WH, BX, BH, out_size, smem);
    }
}

// ============================================================
extern "C" void kernel_launch(void* const* d_in, const int* in_sizes, int n_in,
                              void* d_out, int out_size)
{
    const float* x  = (const float*)d_in[0];
    const float* WX = (const float*)d_in[1];
    const float* WH = (const float*)d_in[2];
    const float* BX = (const float*)d_in[3];
    const float* BH = (const float*)d_in[4];
    float* out = (float*)d_out;

    const size_t smem_bytes = 131072 + 8192 + 16384 + 32768 + 2048;  // 190464
    cudaFuncSetAttribute(lstm_kernel, cudaFuncAttributeMaxDynamicSharedMemorySize,
                         (int)smem_bytes);

    init_kernel<<<64, 256>>>();
    lstm_kernel<<<NWORK + NHELP, 256, smem_bytes>>>(
        out, x, WX, WH, BX, BH, (long long)out_size);
}